// round 11
// baseline (speedup 1.0000x reference)
#include <cuda_runtime.h>
#include <math.h>
#include <stdint.h>

#define NIN   1024
#define KDIM  1024
#define EDIM  256
#define BM    32
#define NPAIRS 1024
#define NGITER 16                      // group-iters per tile (64 k each)
#define ASLAB_G 2176                   // 2 kchunks x 32 rows x 32B + 32 qx floats
#define WSLAB_G 69632                  // 2 kchunks x 1024 cols x 32B + 1024 qw floats
#define STAGE (ASLAB_G + WSLAB_G)      // 71808
#define NSTAGE 3
#define SMEM_DYN (NSTAGE * STAGE)      // 215424
#define NTHREADS 512
#define NWARP 16
#define MARGIN 0.07f

// ---------------- device scratch ----------------
__device__ __align__(128) unsigned char g_xs[(size_t)2048 * NGITER * ASLAB_G];  // 71MB
__device__ __align__(128) unsigned char g_ws[(size_t)NGITER * WSLAB_G];         // 1.1MB
__device__ float g_avgp[KDIM];
__device__ unsigned int g_count;

// ---------------- PTX helpers ----------------
__device__ __forceinline__ uint32_t smem_u32(const void* p) {
    uint32_t a;
    asm("{ .reg .u64 t; cvta.to.shared.u64 t, %1; cvt.u32.u64 %0, t; }" : "=r"(a) : "l"(p));
    return a;
}
__device__ __forceinline__ uint32_t cluster_rank() {
    uint32_t r; asm("mov.u32 %0, %%cluster_ctarank;" : "=r"(r)); return r;
}
#define MBAR_INIT(a, n) \
    asm volatile("mbarrier.init.shared.b64 [%0], %1;" :: "r"(a), "r"((uint32_t)(n)) : "memory")
#define MBAR_EXPECT_TX(a, b) \
    asm volatile("mbarrier.arrive.expect_tx.shared.b64 _, [%0], %1;" :: "r"(a), "r"((uint32_t)(b)) : "memory")
#define MBAR_ARRIVE_RANK(a, rk) \
    asm volatile("{ .reg .b32 ra; mapa.shared::cluster.u32 ra, %0, %1; " \
                 "mbarrier.arrive.shared::cluster.b64 _, [ra]; }" :: "r"(a), "r"(rk) : "memory")
#define MBAR_WAIT(a, p) do { \
    uint32_t _m = (a); uint32_t _p = (p); uint32_t _d; \
    asm volatile("{\n\t.reg .pred q;\n\tmbarrier.try_wait.parity.acquire.cta.shared::cta.b64 q, [%1], %2;\n\tselp.b32 %0,1,0,q;\n\t}" \
        : "=r"(_d) : "r"(_m), "r"(_p) : "memory"); \
    if (!_d) { \
        asm volatile("{\n\t.reg .pred Q;\n\tWL_%=:\n\tmbarrier.try_wait.parity.acquire.cta.shared::cta.b64 Q, [%0], %1, 0x989680;\n\t@Q bra.uni WD_%=;\n\tbra.uni WL_%=;\n\tWD_%=:\n\t}" \
            :: "r"(_m), "r"(_p) : "memory"); \
    } } while (0)
#define CLUSTER_SYNC() do { \
    asm volatile("barrier.cluster.arrive.aligned;" ::: "memory"); \
    asm volatile("barrier.cluster.wait.aligned;" ::: "memory"); } while (0)

__device__ __forceinline__ void bulk_g2s(uint32_t dst, const void* src, uint32_t bytes, uint32_t mbar) {
    asm volatile("cp.async.bulk.shared::cluster.global.mbarrier::complete_tx::bytes [%0], [%1], %2, [%3];"
        :: "r"(dst), "l"(src), "r"(bytes), "r"(mbar) : "memory");
}
__device__ __forceinline__ void bulk_g2s_mc(uint32_t dst, const void* src, uint32_t bytes, uint32_t mbar, uint16_t mask) {
    asm volatile("cp.async.bulk.shared::cluster.global.mbarrier::complete_tx::bytes.multicast::cluster [%0], [%1], %2, [%3], %4;"
        :: "r"(dst), "l"(src), "r"(bytes), "r"(mbar), "h"(mask) : "memory");
}

__device__ __forceinline__ void mma_s8_set(int d[4], uint32_t a0, uint32_t a1, uint32_t a2, uint32_t a3,
                                           uint32_t b0, uint32_t b1, uint32_t z) {
    asm volatile(
        "mma.sync.aligned.m16n8k32.row.col.s32.s8.s8.s32 "
        "{%0,%1,%2,%3}, {%4,%5,%6,%7}, {%8,%9}, {%10,%11,%12,%13};"
        : "=r"(d[0]), "=r"(d[1]), "=r"(d[2]), "=r"(d[3])
        : "r"(a0), "r"(a1), "r"(a2), "r"(a3), "r"(b0), "r"(b1),
          "r"(z), "r"(z), "r"(z), "r"(z));
}
__device__ __forceinline__ void mma_s8_acc(int d[4], uint32_t a0, uint32_t a1, uint32_t a2, uint32_t a3,
                                           uint32_t b0, uint32_t b1) {
    asm volatile(
        "mma.sync.aligned.m16n8k32.row.col.s32.s8.s8.s32 "
        "{%0,%1,%2,%3}, {%4,%5,%6,%7}, {%8,%9}, {%0,%1,%2,%3};"
        : "+r"(d[0]), "+r"(d[1]), "+r"(d[2]), "+r"(d[3])
        : "r"(a0), "r"(a1), "r"(a2), "r"(a3), "r"(b0), "r"(b1));
}

// fast int->float for |v| < 2^22: IADD + FADD on fixed-latency pipes (no I2F)
__device__ __forceinline__ float i2f_fast(int v) {
    return __int_as_float(v + 0x4B400000) - 12582912.0f;
}

__device__ __forceinline__ uint32_t pack_s8x4(float f0, float f1, float f2, float f3, float inv) {
    int i0 = __float2int_rn(f0 * inv), i1 = __float2int_rn(f1 * inv);
    int i2 = __float2int_rn(f2 * inv), i3 = __float2int_rn(f3 * inv);
    return (uint32_t)(i0 & 0xFF) | ((uint32_t)(i1 & 0xFF) << 8) |
           ((uint32_t)(i2 & 0xFF) << 16) | ((uint32_t)i3 << 24);
}

// ---------------- rearrange x: warp-per-row, group-64 int8 quant, no smem ----------------
__global__ __launch_bounds__(512) void rearr_x_kernel(const float* __restrict__ x) {
    const int tid = threadIdx.x;
    const int wid = tid >> 5, lane = tid & 31;
    const int row = blockIdx.x * 16 + wid;
    const int rt = row >> 5, rloc = row & 31;
    const float4* xr = (const float4*)(x + (size_t)row * NIN);

    float4 v[8];
    #pragma unroll
    for (int p = 0; p < 8; p++) v[p] = xr[lane + 32 * p];

    unsigned char* base = g_xs + (size_t)rt * NGITER * ASLAB_G;
    const int kchunk_lo = lane >> 3;                      // 0..3
    const int slot = ((lane & 3) << 1) | ((lane >> 2) & 1);

    #pragma unroll
    for (int p = 0; p < 8; p++) {
        float m = fmaxf(fmaxf(fabsf(v[p].x), fabsf(v[p].y)),
                        fmaxf(fabsf(v[p].z), fabsf(v[p].w)));
        #pragma unroll
        for (int off = 8; off; off >>= 1)
            m = fmaxf(m, __shfl_xor_sync(0xffffffffu, m, off));   // 16-lane segment
        m = fmaxf(m, 1e-20f);
        float inv = 127.0f / m;
        uint32_t pk = pack_s8x4(v[p].x, v[p].y, v[p].z, v[p].w, inv);
        int kchunk = 4 * p + kchunk_lo;
        int giter = kchunk >> 1, kc = kchunk & 1;
        *(uint32_t*)(base + (size_t)giter * ASLAB_G + kc * 1024 + rloc * 32 + slot * 4) = pk;
        if ((lane & 15) == 0) {
            int g = 2 * p + (lane >> 4);
            *(float*)(base + (size_t)g * ASLAB_G + 2048 + rloc * 4) = m * (1.0f / 127.0f);
        }
    }
}

// ---------------- rearrange W: warp-per-column, group-64 int8 quant ----------------
__global__ __launch_bounds__(512) void rearr_w_kernel(const float* __restrict__ W) {
    const int tid = threadIdx.x;
    const int wid = tid >> 5, lane = tid & 31;
    const int ko = blockIdx.x * 16 + wid;
    const float4* wr = (const float4*)(W + (size_t)ko * NIN);

    float4 v[8];
    #pragma unroll
    for (int p = 0; p < 8; p++) v[p] = wr[lane + 32 * p];

    const int kchunk_lo = lane >> 3;
    const int slot = ((lane & 3) << 1) | ((lane >> 2) & 1);

    #pragma unroll
    for (int p = 0; p < 8; p++) {
        float m = fmaxf(fmaxf(fabsf(v[p].x), fabsf(v[p].y)),
                        fmaxf(fabsf(v[p].z), fabsf(v[p].w)));
        #pragma unroll
        for (int off = 8; off; off >>= 1)
            m = fmaxf(m, __shfl_xor_sync(0xffffffffu, m, off));
        m = fmaxf(m, 1e-20f);
        float inv = 127.0f / m;
        uint32_t pk = pack_s8x4(v[p].x, v[p].y, v[p].z, v[p].w, inv);
        int kchunk = 4 * p + kchunk_lo;
        int giter = kchunk >> 1, kc = kchunk & 1;
        *(uint32_t*)(g_ws + (size_t)giter * WSLAB_G + kc * 32768 + ko * 32 + slot * 4) = pk;
        if ((lane & 15) == 0) {
            int g = 2 * p + (lane >> 4);
            *(float*)(g_ws + (size_t)g * WSLAB_G + 65536 + ko * 4) = m * (1.0f / 127.0f);
        }
    }
}

// ---------------- persistent fused int8 GEMM (group-64 dequant) + epilogue ----------------
__global__ __launch_bounds__(NTHREADS, 1) __cluster_dims__(2, 1, 1)
void fused_vq_kernel(const float* __restrict__ x, const float* __restrict__ W,
                     const float* __restrict__ gum, const float* __restrict__ bias,
                     const float* __restrict__ cb, float* __restrict__ out, int B)
{
    extern __shared__ __align__(128) unsigned char smem[];
    __shared__ __align__(8) unsigned long long mb_full[NSTAGE], mb_empty[NSTAGE];
    __shared__ float swmax[NWARP][32];
    __shared__ int   swarg[NWARP][32];
    __shared__ float swsum[NWARP][32];
    __shared__ float frow[32], finv[32];
    __shared__ int   rowcnt[32], srowm[32];
    __shared__ int   rowcols[32][8];
    __shared__ int   s_amblist[32];
    __shared__ int   s_namb;
    __shared__ float sred[NWARP];
    __shared__ int   sIsLast;

    const int tid  = threadIdx.x;
    const int wid  = tid >> 5;
    const int lane = tid & 31;
    const int r0   = lane >> 2;
    const int q    = lane & 3;
    const uint32_t rank = cluster_rank();
    const int cl   = blockIdx.x >> 1;
    const int ncl  = gridDim.x >> 1;
    const int wbase = wid * 64;

    const int ntiles = (NPAIRS - 1 - cl) / ncl + 1;
    const int total_its = ntiles * NGITER;

    const uint32_t smem_b = smem_u32(smem);
    uint32_t full_a[NSTAGE], empty_a[NSTAGE];
    #pragma unroll
    for (int s = 0; s < NSTAGE; s++) {
        full_a[s]  = smem_u32(&mb_full[s]);
        empty_a[s] = smem_u32(&mb_empty[s]);
    }
    if (tid == 0) {
        #pragma unroll
        for (int s = 0; s < NSTAGE; s++) { MBAR_INIT(full_a[s], 1); MBAR_INIT(empty_a[s], 2); }
    }
    __syncthreads();
    CLUSTER_SYNC();

    if (tid == 0) {
        #pragma unroll
        for (int i = 0; i < NSTAGE; i++) {
            MBAR_EXPECT_TX(full_a[i], STAGE);
            bulk_g2s(smem_b + i * STAGE,
                     g_xs + (size_t)((2 * cl + rank) * NGITER + i) * ASLAB_G, ASLAB_G, full_a[i]);
            bulk_g2s_mc(smem_b + i * STAGE + ASLAB_G + rank * (WSLAB_G / 2),
                        g_ws + (size_t)i * WSLAB_G + rank * (WSLAB_G / 2),
                        WSLAB_G / 2, full_a[i], (uint16_t)0x3);
        }
    }

    const uint32_t zreg = 0;
    int it = 0, s = 0, ph = 0;
    for (int t = 0; t < ntiles; t++) {
        const int p = cl + t * ncl;
        const int rowbase = (2 * p + rank) * BM;

        float f[2][8][4];
        #pragma unroll
        for (int m = 0; m < 2; m++)
            #pragma unroll
            for (int j = 0; j < 8; j++)
                #pragma unroll
                for (int v = 0; v < 4; v++) f[m][j][v] = 0.0f;

        // -------- mainloop: 16 group-iters (64 k each, 2 kchunks) --------
        for (int g = 0; g < NGITER; g++) {
            MBAR_WAIT(full_a[s], ph);
            const unsigned char* base = smem + s * STAGE;
            const uint32_t* As0 = (const uint32_t*)(base);
            const uint32_t* As1 = (const uint32_t*)(base + 1024);
            const float*    qxp = (const float*)(base + 2048);
            const uint32_t* Ws0 = (const uint32_t*)(base + ASLAB_G);
            const uint32_t* Ws1 = (const uint32_t*)(base + ASLAB_G + 32768);
            const float*    qwT = (const float*)(base + ASLAB_G + 65536);

            float qxv[4];
            qxv[0] = qxp[r0];      qxv[1] = qxp[r0 + 8];
            qxv[2] = qxp[r0 + 16]; qxv[3] = qxp[r0 + 24];

            uint2 aA0[2], aB0[2], aA1[2], aB1[2];
            #pragma unroll
            for (int mt = 0; mt < 2; mt++) {
                aA0[mt] = *(const uint2*)&As0[(mt * 16 + r0) * 8 + 2 * q];
                aB0[mt] = *(const uint2*)&As0[(mt * 16 + r0 + 8) * 8 + 2 * q];
                aA1[mt] = *(const uint2*)&As1[(mt * 16 + r0) * 8 + 2 * q];
                aB1[mt] = *(const uint2*)&As1[(mt * 16 + r0 + 8) * 8 + 2 * q];
            }
            #pragma unroll
            for (int j = 0; j < 8; j++) {
                const int brow = wbase + j * 8 + r0;
                uint2 b0 = *(const uint2*)&Ws0[brow * 8 + 2 * q];
                uint2 b1 = *(const uint2*)&Ws1[brow * 8 + 2 * q];
                float2 qw2 = *(const float2*)&qwT[wbase + j * 8 + 2 * q];
                float sc[4][2];
                #pragma unroll
                for (int ri = 0; ri < 4; ri++) {
                    sc[ri][0] = qxv[ri] * qw2.x;
                    sc[ri][1] = qxv[ri] * qw2.y;
                }
                #pragma unroll
                for (int mt = 0; mt < 2; mt++) {
                    int dt[4];
                    mma_s8_set(dt, aA0[mt].x, aB0[mt].x, aA0[mt].y, aB0[mt].y, b0.x, b0.y, zreg);
                    mma_s8_acc(dt, aA1[mt].x, aB1[mt].x, aA1[mt].y, aB1[mt].y, b1.x, b1.y);
                    f[mt][j][0] = fmaf(i2f_fast(dt[0]), sc[mt * 2 + 0][0], f[mt][j][0]);
                    f[mt][j][1] = fmaf(i2f_fast(dt[1]), sc[mt * 2 + 0][1], f[mt][j][1]);
                    f[mt][j][2] = fmaf(i2f_fast(dt[2]), sc[mt * 2 + 1][0], f[mt][j][2]);
                    f[mt][j][3] = fmaf(i2f_fast(dt[3]), sc[mt * 2 + 1][1], f[mt][j][3]);
                }
            }
            __syncthreads();
            if (tid == 0) {
                MBAR_ARRIVE_RANK(empty_a[s], 0);
                MBAR_ARRIVE_RANK(empty_a[s], 1);
                const int git = it + NSTAGE;
                if (git < total_its) {
                    const int pi = git / NGITER, gg = git % NGITER;
                    const int pp = cl + pi * ncl;
                    MBAR_WAIT(empty_a[s], ph);
                    MBAR_EXPECT_TX(full_a[s], STAGE);
                    bulk_g2s(smem_b + s * STAGE,
                             g_xs + (size_t)((2 * pp + rank) * NGITER + gg) * ASLAB_G,
                             ASLAB_G, full_a[s]);
                    bulk_g2s_mc(smem_b + s * STAGE + ASLAB_G + rank * (WSLAB_G / 2),
                                g_ws + (size_t)gg * WSLAB_G + rank * (WSLAB_G / 2),
                                WSLAB_G / 2, full_a[s], (uint16_t)0x3);
                }
            }
            it++; s++; if (s == NSTAGE) { s = 0; ph ^= 1; }
        }

        // -------- epilogue --------
        // step 1: + bias + gumbel; per-thread row max/arg
        float bcol[8][2];
        #pragma unroll
        for (int j = 0; j < 8; j++) {
            float2 b2 = *(const float2*)(bias + wbase + j * 8 + 2 * q);
            bcol[j][0] = b2.x; bcol[j][1] = b2.y;
        }
        float vmax[4]; int varg[4];
        #pragma unroll
        for (int row_i = 0; row_i < 4; row_i++) {
            const int grow = rowbase + r0 + row_i * 8;
            const int mt = row_i >> 1, hr = row_i & 1;
            float vm = -1e30f; int va = 0;
            #pragma unroll
            for (int j = 0; j < 8; j++) {
                const int col = wbase + j * 8 + 2 * q;
                float2 g2 = *(const float2*)(gum + (size_t)grow * KDIM + col);
                float v0 = f[mt][j][hr * 2 + 0] + bcol[j][0] + g2.x;
                float v1 = f[mt][j][hr * 2 + 1] + bcol[j][1] + g2.y;
                f[mt][j][hr * 2 + 0] = v0;
                f[mt][j][hr * 2 + 1] = v1;
                if (v0 > vm) { vm = v0; va = col; }
                if (v1 > vm) { vm = v1; va = col + 1; }
            }
            vmax[row_i] = vm; varg[row_i] = va;
        }
        #pragma unroll
        for (int off = 1; off <= 2; off <<= 1)
            #pragma unroll
            for (int row_i = 0; row_i < 4; row_i++) {
                float ov = __shfl_xor_sync(0xffffffffu, vmax[row_i], off);
                int   oa = __shfl_xor_sync(0xffffffffu, varg[row_i], off);
                if (ov > vmax[row_i] || (ov == vmax[row_i] && oa < varg[row_i])) {
                    vmax[row_i] = ov; varg[row_i] = oa;
                }
            }
        if (q == 0) {
            #pragma unroll
            for (int row_i = 0; row_i < 4; row_i++) {
                swmax[wid][r0 + row_i * 8] = vmax[row_i];
                swarg[wid][r0 + row_i * 8] = varg[row_i];
            }
        }
        __syncthreads();
        if (tid < 32) {
            float best = -1e30f; int barg = KDIM;
            #pragma unroll
            for (int w = 0; w < NWARP; w++) {
                float v = swmax[w][tid]; int a = swarg[w][tid];
                if (v > best || (v == best && a < barg)) { best = v; barg = a; }
            }
            frow[tid] = best; srowm[tid] = barg; rowcnt[tid] = 0;
            if (tid == 0) s_namb = 0;
        }
        __syncthreads();
        // step 3: candidates + exp + row partial sums
        float psum[4] = {0.f, 0.f, 0.f, 0.f};
        #pragma unroll
        for (int row_i = 0; row_i < 4; row_i++) {
            const int row = r0 + row_i * 8;
            const int mt = row_i >> 1, hr = row_i & 1;
            const float rm = frow[row];
            const float th = rm - MARGIN;
            #pragma unroll
            for (int j = 0; j < 8; j++) {
                #pragma unroll
                for (int half = 0; half < 2; half++) {
                    float v = f[mt][j][hr * 2 + half];
                    if (v >= th) {
                        int pos = atomicAdd(&rowcnt[row], 1);
                        if (pos < 8) rowcols[row][pos] = wbase + j * 8 + 2 * q + half;
                    }
                    float e = __expf(v - rm);
                    f[mt][j][hr * 2 + half] = e;
                    psum[row_i] += e;
                }
            }
        }
        #pragma unroll
        for (int off = 1; off <= 2; off <<= 1)
            #pragma unroll
            for (int row_i = 0; row_i < 4; row_i++)
                psum[row_i] += __shfl_xor_sync(0xffffffffu, psum[row_i], off);
        if (q == 0) {
            #pragma unroll
            for (int row_i = 0; row_i < 4; row_i++)
                swsum[wid][r0 + row_i * 8] = psum[row_i];
        }
        __syncthreads();
        if (tid < 32) {
            float sm = 0.0f;
            #pragma unroll
            for (int w = 0; w < NWARP; w++) sm += swsum[w][tid];
            finv[tid] = 1.0f / sm;
            if (rowcnt[tid] > 1) {
                int ix = atomicAdd(&s_namb, 1);
                s_amblist[ix] = tid;
            }
        }
        __syncthreads();
        // step 5: avg_p
        #pragma unroll
        for (int j = 0; j < 8; j++) {
            #pragma unroll
            for (int half = 0; half < 2; half++) {
                float tt = 0.0f;
                #pragma unroll
                for (int row_i = 0; row_i < 4; row_i++) {
                    const int mt = row_i >> 1, hr = row_i & 1;
                    tt += f[mt][j][hr * 2 + half] * finv[r0 + row_i * 8];
                }
                tt += __shfl_xor_sync(0xffffffffu, tt, 4);
                tt += __shfl_xor_sync(0xffffffffu, tt, 8);
                tt += __shfl_xor_sync(0xffffffffu, tt, 16);
                if (r0 == 0) atomicAdd(&g_avgp[wbase + j * 8 + 2 * q + half], tt);
            }
        }
        // step 6: inline fp32 refinement (warp per ambiguous row)
        const int na = s_namb;
        for (int a = wid; a < na; a += NWARP) {
            const int row = s_amblist[a];
            const int nc  = rowcnt[row];
            const int grow = rowbase + row;
            const float* xr = x + (size_t)grow * NIN;
            float xv[32];
            #pragma unroll
            for (int u = 0; u < 32; u++) xv[u] = xr[lane + u * 32];
            float best = -1e30f; int bestc = KDIM;
            if (nc <= 8) {
                for (int ti = 0; ti < nc; ti++) {
                    const int c = rowcols[row][ti];
                    const float* wr = W + (size_t)c * NIN;
                    float sm = 0.0f;
                    #pragma unroll
                    for (int u = 0; u < 32; u++) sm = fmaf(xv[u], wr[lane + u * 32], sm);
                    #pragma unroll
                    for (int off = 16; off; off >>= 1)
                        sm += __shfl_xor_sync(0xffffffffu, sm, off);
                    float val = sm + bias[c] + gum[(size_t)grow * KDIM + c];
                    if (val > best || (val == best && c < bestc)) { best = val; bestc = c; }
                }
            } else {
                for (int c = 0; c < KDIM; c++) {
                    const float* wr = W + (size_t)c * NIN;
                    float sm = 0.0f;
                    #pragma unroll
                    for (int u = 0; u < 32; u++) sm = fmaf(xv[u], wr[lane + u * 32], sm);
                    #pragma unroll
                    for (int off = 16; off; off >>= 1)
                        sm += __shfl_xor_sync(0xffffffffu, sm, off);
                    float val = sm + bias[c] + gum[(size_t)grow * KDIM + c];
                    if (val > best) { best = val; bestc = c; }
                }
            }
            if (lane == 0) srowm[row] = bestc;
        }
        __syncthreads();
        // step 7: m + z_q
        if (tid < 32) out[(size_t)B * EDIM + rowbase + tid] = (float)srowm[tid];
        #pragma unroll
        for (int g2 = 0; g2 < 4; g2++) {
            int idx = g2 * NTHREADS + tid;
            int row = idx >> 6, v = idx & 63;
            int arg = srowm[row];
            float4 cv = *(const float4*)(cb + (size_t)arg * EDIM + v * 4);
            *(float4*)(out + (size_t)(rowbase + row) * EDIM + v * 4) = cv;
        }
        __syncthreads();
    }

    // -------- diversity finisher --------
    __threadfence();
    if (tid == 0) {
        unsigned int old = atomicAdd(&g_count, 1u);
        sIsLast = (old == gridDim.x - 1) ? 1 : 0;
    }
    __syncthreads();
    if (sIsLast) {
        const float invB = 1.0f / (float)B;
        const float logK = logf((float)KDIM);
        float sdiv = 0.0f;
        for (int c = tid; c < KDIM; c += NTHREADS) {
            float p2 = g_avgp[c] * invB;
            sdiv += p2 * (logf(fmaxf(p2, 1e-9f)) + logK);
            g_avgp[c] = 0.0f;
        }
        #pragma unroll
        for (int off = 16; off; off >>= 1)
            sdiv += __shfl_xor_sync(0xffffffffu, sdiv, off);
        if (lane == 0) sred[wid] = sdiv;
        __syncthreads();
        if (tid == 0) {
            float tt = 0.0f;
            #pragma unroll
            for (int w = 0; w < NWARP; w++) tt += sred[w];
            size_t base = (size_t)B * EDIM + B;
            out[base]     = tt;
            out[base + 1] = 0.0f;
            g_count = 0u;
        }
    }
    CLUSTER_SYNC();
}

// ---------------- launch ----------------
extern "C" void kernel_launch(void* const* d_in, const int* in_sizes, int n_in,
                              void* d_out, int out_size) {
    const float* x    = (const float*)d_in[0];
    const float* gum  = (const float*)d_in[1];
    const float* W    = (const float*)d_in[2];
    const float* bias = (const float*)d_in[3];
    const float* cb   = (const float*)d_in[4];
    float* out = (float*)d_out;

    const int B = in_sizes[0] / NIN;             // 65536

    static int nsm = 0;
    if (nsm == 0) {
        cudaDeviceGetAttribute(&nsm, cudaDevAttrMultiProcessorCount, 0);
        nsm &= ~1;
        if (nsm <= 0) nsm = 148;
        cudaFuncSetAttribute(fused_vq_kernel, cudaFuncAttributeMaxDynamicSharedMemorySize, SMEM_DYN);
    }

    rearr_x_kernel<<<B / 16, 512>>>(x);
    rearr_w_kernel<<<KDIM / 16, 512>>>(W);
    fused_vq_kernel<<<nsm, NTHREADS, SMEM_DYN>>>(x, W, gum, bias, cb, out, B);
}

// round 12
// speedup vs baseline: 1.5425x; 1.5425x over previous
#include <cuda_runtime.h>
#include <math.h>
#include <stdint.h>

#define NIN   1024
#define KDIM  1024
#define EDIM  256
#define BM    32
#define NPAIRS 1024
#define NGITER 16                      // group-iters per tile (64 k each)
#define ASLAB_G 2176                   // 2 kchunks x 32 rows x 32B + 32 qx floats
#define WSLAB_G 69632                  // 2 kchunks x 1024 cols x 32B + 1024 qw floats
#define STAGE (ASLAB_G + WSLAB_G)      // 71808
#define NSTAGE 3
#define SMEM_DYN (NSTAGE * STAGE)      // 215424
#define NTHREADS 512
#define NWARP 16
#define MARGIN 0.07f

// ---------------- device scratch ----------------
__device__ __align__(128) unsigned char g_xs[(size_t)2048 * NGITER * ASLAB_G];  // 71MB
__device__ __align__(128) unsigned char g_ws[(size_t)NGITER * WSLAB_G];         // 1.1MB
__device__ float g_avgp[KDIM];
__device__ unsigned int g_count;

// ---------------- PTX helpers ----------------
__device__ __forceinline__ uint32_t smem_u32(const void* p) {
    uint32_t a;
    asm("{ .reg .u64 t; cvta.to.shared.u64 t, %1; cvt.u32.u64 %0, t; }" : "=r"(a) : "l"(p));
    return a;
}
__device__ __forceinline__ uint32_t cluster_rank() {
    uint32_t r; asm("mov.u32 %0, %%cluster_ctarank;" : "=r"(r)); return r;
}
#define MBAR_INIT(a, n) \
    asm volatile("mbarrier.init.shared.b64 [%0], %1;" :: "r"(a), "r"((uint32_t)(n)) : "memory")
#define MBAR_EXPECT_TX(a, b) \
    asm volatile("mbarrier.arrive.expect_tx.shared.b64 _, [%0], %1;" :: "r"(a), "r"((uint32_t)(b)) : "memory")
#define MBAR_ARRIVE_RANK(a, rk) \
    asm volatile("{ .reg .b32 ra; mapa.shared::cluster.u32 ra, %0, %1; " \
                 "mbarrier.arrive.shared::cluster.b64 _, [ra]; }" :: "r"(a), "r"(rk) : "memory")
#define MBAR_WAIT(a, p) do { \
    uint32_t _m = (a); uint32_t _p = (p); uint32_t _d; \
    asm volatile("{\n\t.reg .pred q;\n\tmbarrier.try_wait.parity.acquire.cta.shared::cta.b64 q, [%1], %2;\n\tselp.b32 %0,1,0,q;\n\t}" \
        : "=r"(_d) : "r"(_m), "r"(_p) : "memory"); \
    if (!_d) { \
        asm volatile("{\n\t.reg .pred Q;\n\tWL_%=:\n\tmbarrier.try_wait.parity.acquire.cta.shared::cta.b64 Q, [%0], %1, 0x989680;\n\t@Q bra.uni WD_%=;\n\tbra.uni WL_%=;\n\tWD_%=:\n\t}" \
            :: "r"(_m), "r"(_p) : "memory"); \
    } } while (0)
#define CLUSTER_SYNC() do { \
    asm volatile("barrier.cluster.arrive.aligned;" ::: "memory"); \
    asm volatile("barrier.cluster.wait.aligned;" ::: "memory"); } while (0)

__device__ __forceinline__ void bulk_g2s(uint32_t dst, const void* src, uint32_t bytes, uint32_t mbar) {
    asm volatile("cp.async.bulk.shared::cluster.global.mbarrier::complete_tx::bytes [%0], [%1], %2, [%3];"
        :: "r"(dst), "l"(src), "r"(bytes), "r"(mbar) : "memory");
}
__device__ __forceinline__ void bulk_g2s_mc(uint32_t dst, const void* src, uint32_t bytes, uint32_t mbar, uint16_t mask) {
    asm volatile("cp.async.bulk.shared::cluster.global.mbarrier::complete_tx::bytes.multicast::cluster [%0], [%1], %2, [%3], %4;"
        :: "r"(dst), "l"(src), "r"(bytes), "r"(mbar), "h"(mask) : "memory");
}

__device__ __forceinline__ void mma_s8_set(int d[4], uint32_t a0, uint32_t a1, uint32_t a2, uint32_t a3,
                                           uint32_t b0, uint32_t b1, uint32_t z) {
    asm volatile(
        "mma.sync.aligned.m16n8k32.row.col.s32.s8.s8.s32 "
        "{%0,%1,%2,%3}, {%4,%5,%6,%7}, {%8,%9}, {%10,%11,%12,%13};"
        : "=r"(d[0]), "=r"(d[1]), "=r"(d[2]), "=r"(d[3])
        : "r"(a0), "r"(a1), "r"(a2), "r"(a3), "r"(b0), "r"(b1),
          "r"(z), "r"(z), "r"(z), "r"(z));
}

// fast int->float for |v| < 2^22: IADD + FADD on fixed-latency pipes (no I2F)
__device__ __forceinline__ float i2f_fast(int v) {
    return __int_as_float(v + 0x4B400000) - 12582912.0f;
}

__device__ __forceinline__ uint32_t pack_s8x4(float f0, float f1, float f2, float f3, float inv) {
    int i0 = __float2int_rn(f0 * inv), i1 = __float2int_rn(f1 * inv);
    int i2 = __float2int_rn(f2 * inv), i3 = __float2int_rn(f3 * inv);
    return (uint32_t)(i0 & 0xFF) | ((uint32_t)(i1 & 0xFF) << 8) |
           ((uint32_t)(i2 & 0xFF) << 16) | ((uint32_t)i3 << 24);
}

// ---------------- rearrange x: warp-per-row, group-64 int8 quant, no smem ----------------
__global__ __launch_bounds__(512) void rearr_x_kernel(const float* __restrict__ x) {
    const int tid = threadIdx.x;
    const int wid = tid >> 5, lane = tid & 31;
    const int row = blockIdx.x * 16 + wid;
    const int rt = row >> 5, rloc = row & 31;
    const float4* xr = (const float4*)(x + (size_t)row * NIN);

    float4 v[8];
    #pragma unroll
    for (int p = 0; p < 8; p++) v[p] = xr[lane + 32 * p];

    unsigned char* base = g_xs + (size_t)rt * NGITER * ASLAB_G;
    const int kchunk_lo = lane >> 3;                      // 0..3
    const int slot = ((lane & 3) << 1) | ((lane >> 2) & 1);

    #pragma unroll
    for (int p = 0; p < 8; p++) {
        float m = fmaxf(fmaxf(fabsf(v[p].x), fabsf(v[p].y)),
                        fmaxf(fabsf(v[p].z), fabsf(v[p].w)));
        #pragma unroll
        for (int off = 8; off; off >>= 1)
            m = fmaxf(m, __shfl_xor_sync(0xffffffffu, m, off));   // 16-lane segment
        m = fmaxf(m, 1e-20f);
        float inv = 127.0f / m;
        uint32_t pk = pack_s8x4(v[p].x, v[p].y, v[p].z, v[p].w, inv);
        int kchunk = 4 * p + kchunk_lo;
        int giter = kchunk >> 1, kc = kchunk & 1;
        *(uint32_t*)(base + (size_t)giter * ASLAB_G + kc * 1024 + rloc * 32 + slot * 4) = pk;
        if ((lane & 15) == 0) {
            int g = 2 * p + (lane >> 4);
            *(float*)(base + (size_t)g * ASLAB_G + 2048 + rloc * 4) = m * (1.0f / 127.0f);
        }
    }
}

// ---------------- rearrange W: warp-per-column, group-64 int8 quant ----------------
__global__ __launch_bounds__(512) void rearr_w_kernel(const float* __restrict__ W) {
    const int tid = threadIdx.x;
    const int wid = tid >> 5, lane = tid & 31;
    const int ko = blockIdx.x * 16 + wid;
    const float4* wr = (const float4*)(W + (size_t)ko * NIN);

    float4 v[8];
    #pragma unroll
    for (int p = 0; p < 8; p++) v[p] = wr[lane + 32 * p];

    const int kchunk_lo = lane >> 3;
    const int slot = ((lane & 3) << 1) | ((lane >> 2) & 1);

    #pragma unroll
    for (int p = 0; p < 8; p++) {
        float m = fmaxf(fmaxf(fabsf(v[p].x), fabsf(v[p].y)),
                        fmaxf(fabsf(v[p].z), fabsf(v[p].w)));
        #pragma unroll
        for (int off = 8; off; off >>= 1)
            m = fmaxf(m, __shfl_xor_sync(0xffffffffu, m, off));
        m = fmaxf(m, 1e-20f);
        float inv = 127.0f / m;
        uint32_t pk = pack_s8x4(v[p].x, v[p].y, v[p].z, v[p].w, inv);
        int kchunk = 4 * p + kchunk_lo;
        int giter = kchunk >> 1, kc = kchunk & 1;
        *(uint32_t*)(g_ws + (size_t)giter * WSLAB_G + kc * 32768 + ko * 32 + slot * 4) = pk;
        if ((lane & 15) == 0) {
            int g = 2 * p + (lane >> 4);
            *(float*)(g_ws + (size_t)g * WSLAB_G + 65536 + ko * 4) = m * (1.0f / 127.0f);
        }
    }
}

// ---------------- persistent fused int8 GEMM (group-64 dequant) + epilogue ----------------
__global__ __launch_bounds__(NTHREADS, 1) __cluster_dims__(2, 1, 1)
void fused_vq_kernel(const float* __restrict__ x, const float* __restrict__ W,
                     const float* __restrict__ gum, const float* __restrict__ bias,
                     const float* __restrict__ cb, float* __restrict__ out, int B)
{
    extern __shared__ __align__(128) unsigned char smem[];
    __shared__ __align__(8) unsigned long long mb_full[NSTAGE], mb_empty[NSTAGE];
    __shared__ float swmax[NWARP][32];
    __shared__ int   swarg[NWARP][32];
    __shared__ float swsum[NWARP][32];
    __shared__ float frow[32], finv[32];
    __shared__ int   rowcnt[32], srowm[32];
    __shared__ int   rowcols[32][8];
    __shared__ int   s_amblist[32];
    __shared__ int   s_namb;
    __shared__ float sred[NWARP];
    __shared__ int   sIsLast;

    const int tid  = threadIdx.x;
    const int wid  = tid >> 5;
    const int lane = tid & 31;
    const int r0   = lane >> 2;
    const int q    = lane & 3;
    const uint32_t rank = cluster_rank();
    const int cl   = blockIdx.x >> 1;
    const int ncl  = gridDim.x >> 1;
    const int wbase = wid * 64;

    const int ntiles = (NPAIRS - 1 - cl) / ncl + 1;
    const int total_its = ntiles * NGITER;

    const uint32_t smem_b = smem_u32(smem);
    uint32_t full_a[NSTAGE], empty_a[NSTAGE];
    #pragma unroll
    for (int s = 0; s < NSTAGE; s++) {
        full_a[s]  = smem_u32(&mb_full[s]);
        empty_a[s] = smem_u32(&mb_empty[s]);
    }
    if (tid == 0) {
        #pragma unroll
        for (int s = 0; s < NSTAGE; s++) { MBAR_INIT(full_a[s], 1); MBAR_INIT(empty_a[s], 2); }
    }
    __syncthreads();
    CLUSTER_SYNC();

    if (tid == 0) {
        #pragma unroll
        for (int i = 0; i < NSTAGE; i++) {
            MBAR_EXPECT_TX(full_a[i], STAGE);
            bulk_g2s(smem_b + i * STAGE,
                     g_xs + (size_t)((2 * cl + rank) * NGITER + i) * ASLAB_G, ASLAB_G, full_a[i]);
            bulk_g2s_mc(smem_b + i * STAGE + ASLAB_G + rank * (WSLAB_G / 2),
                        g_ws + (size_t)i * WSLAB_G + rank * (WSLAB_G / 2),
                        WSLAB_G / 2, full_a[i], (uint16_t)0x3);
        }
    }

    int it = 0, s = 0, ph = 0;
    for (int t = 0; t < ntiles; t++) {
        const int p = cl + t * ncl;
        const int rowbase = (2 * p + rank) * BM;

        float f[2][8][4];
        #pragma unroll
        for (int m = 0; m < 2; m++)
            #pragma unroll
            for (int j = 0; j < 8; j++)
                #pragma unroll
                for (int v = 0; v < 4; v++) f[m][j][v] = 0.0f;

        // -------- mainloop: 16 group-iters, per-kchunk MMA+dequant (reg-frugal) --------
        for (int g = 0; g < NGITER; g++) {
            MBAR_WAIT(full_a[s], ph);
            const unsigned char* base = smem + s * STAGE;
            const float* qxp = (const float*)(base + 2048);
            const float* qwT = (const float*)(base + ASLAB_G + 65536);

            float qxv[4];
            qxv[0] = qxp[r0];      qxv[1] = qxp[r0 + 8];
            qxv[2] = qxp[r0 + 16]; qxv[3] = qxp[r0 + 24];

            #pragma unroll
            for (int kc = 0; kc < 2; kc++) {
                const uint32_t* As = (const uint32_t*)(base + kc * 1024);
                const uint32_t* Ws = (const uint32_t*)(base + ASLAB_G + kc * 32768);
                uint2 a[2][2];
                #pragma unroll
                for (int mt = 0; mt < 2; mt++) {
                    a[mt][0] = *(const uint2*)&As[(mt * 16 + r0) * 8 + 2 * q];
                    a[mt][1] = *(const uint2*)&As[(mt * 16 + r0 + 8) * 8 + 2 * q];
                }
                #pragma unroll
                for (int j = 0; j < 8; j++) {
                    uint2 b = *(const uint2*)&Ws[(wbase + j * 8 + r0) * 8 + 2 * q];
                    float2 qw2 = *(const float2*)&qwT[wbase + j * 8 + 2 * q];
                    #pragma unroll
                    for (int mt = 0; mt < 2; mt++) {
                        int dt[4];
                        mma_s8_set(dt, a[mt][0].x, a[mt][1].x, a[mt][0].y, a[mt][1].y,
                                   b.x, b.y, 0u);
                        float s0 = qxv[mt * 2]     * qw2.x;
                        float s1 = qxv[mt * 2]     * qw2.y;
                        float s2 = qxv[mt * 2 + 1] * qw2.x;
                        float s3 = qxv[mt * 2 + 1] * qw2.y;
                        f[mt][j][0] = fmaf(i2f_fast(dt[0]), s0, f[mt][j][0]);
                        f[mt][j][1] = fmaf(i2f_fast(dt[1]), s1, f[mt][j][1]);
                        f[mt][j][2] = fmaf(i2f_fast(dt[2]), s2, f[mt][j][2]);
                        f[mt][j][3] = fmaf(i2f_fast(dt[3]), s3, f[mt][j][3]);
                    }
                }
            }
            __syncthreads();
            if (tid == 0) {
                MBAR_ARRIVE_RANK(empty_a[s], 0);
                MBAR_ARRIVE_RANK(empty_a[s], 1);
                const int git = it + NSTAGE;
                if (git < total_its) {
                    const int pi = git / NGITER, gg = git % NGITER;
                    const int pp = cl + pi * ncl;
                    MBAR_WAIT(empty_a[s], ph);
                    MBAR_EXPECT_TX(full_a[s], STAGE);
                    bulk_g2s(smem_b + s * STAGE,
                             g_xs + (size_t)((2 * pp + rank) * NGITER + gg) * ASLAB_G,
                             ASLAB_G, full_a[s]);
                    bulk_g2s_mc(smem_b + s * STAGE + ASLAB_G + rank * (WSLAB_G / 2),
                                g_ws + (size_t)gg * WSLAB_G + rank * (WSLAB_G / 2),
                                WSLAB_G / 2, full_a[s], (uint16_t)0x3);
                }
            }
            it++; s++; if (s == NSTAGE) { s = 0; ph ^= 1; }
        }

        // -------- epilogue --------
        // step 1: + bias + gumbel; per-thread row max/arg
        float vmax[4]; int varg[4];
        #pragma unroll
        for (int row_i = 0; row_i < 4; row_i++) {
            const int grow = rowbase + r0 + row_i * 8;
            const int mt = row_i >> 1, hr = row_i & 1;
            float vm = -1e30f; int va = 0;
            #pragma unroll
            for (int j = 0; j < 8; j++) {
                const int col = wbase + j * 8 + 2 * q;
                float2 b2 = *(const float2*)(bias + col);
                float2 g2 = *(const float2*)(gum + (size_t)grow * KDIM + col);
                float v0 = f[mt][j][hr * 2 + 0] + b2.x + g2.x;
                float v1 = f[mt][j][hr * 2 + 1] + b2.y + g2.y;
                f[mt][j][hr * 2 + 0] = v0;
                f[mt][j][hr * 2 + 1] = v1;
                if (v0 > vm) { vm = v0; va = col; }
                if (v1 > vm) { vm = v1; va = col + 1; }
            }
            vmax[row_i] = vm; varg[row_i] = va;
        }
        #pragma unroll
        for (int off = 1; off <= 2; off <<= 1)
            #pragma unroll
            for (int row_i = 0; row_i < 4; row_i++) {
                float ov = __shfl_xor_sync(0xffffffffu, vmax[row_i], off);
                int   oa = __shfl_xor_sync(0xffffffffu, varg[row_i], off);
                if (ov > vmax[row_i] || (ov == vmax[row_i] && oa < varg[row_i])) {
                    vmax[row_i] = ov; varg[row_i] = oa;
                }
            }
        if (q == 0) {
            #pragma unroll
            for (int row_i = 0; row_i < 4; row_i++) {
                swmax[wid][r0 + row_i * 8] = vmax[row_i];
                swarg[wid][r0 + row_i * 8] = varg[row_i];
            }
        }
        __syncthreads();
        if (tid < 32) {
            float best = -1e30f; int barg = KDIM;
            #pragma unroll
            for (int w = 0; w < NWARP; w++) {
                float v = swmax[w][tid]; int a = swarg[w][tid];
                if (v > best || (v == best && a < barg)) { best = v; barg = a; }
            }
            frow[tid] = best; srowm[tid] = barg; rowcnt[tid] = 0;
            if (tid == 0) s_namb = 0;
        }
        __syncthreads();
        // step 3: candidates + exp + row partial sums
        float psum[4] = {0.f, 0.f, 0.f, 0.f};
        #pragma unroll
        for (int row_i = 0; row_i < 4; row_i++) {
            const int row = r0 + row_i * 8;
            const int mt = row_i >> 1, hr = row_i & 1;
            const float rm = frow[row];
            const float th = rm - MARGIN;
            #pragma unroll
            for (int j = 0; j < 8; j++) {
                #pragma unroll
                for (int half = 0; half < 2; half++) {
                    float v = f[mt][j][hr * 2 + half];
                    if (v >= th) {
                        int pos = atomicAdd(&rowcnt[row], 1);
                        if (pos < 8) rowcols[row][pos] = wbase + j * 8 + 2 * q + half;
                    }
                    float e = __expf(v - rm);
                    f[mt][j][hr * 2 + half] = e;
                    psum[row_i] += e;
                }
            }
        }
        #pragma unroll
        for (int off = 1; off <= 2; off <<= 1)
            #pragma unroll
            for (int row_i = 0; row_i < 4; row_i++)
                psum[row_i] += __shfl_xor_sync(0xffffffffu, psum[row_i], off);
        if (q == 0) {
            #pragma unroll
            for (int row_i = 0; row_i < 4; row_i++)
                swsum[wid][r0 + row_i * 8] = psum[row_i];
        }
        __syncthreads();
        if (tid < 32) {
            float sm = 0.0f;
            #pragma unroll
            for (int w = 0; w < NWARP; w++) sm += swsum[w][tid];
            finv[tid] = 1.0f / sm;
            if (rowcnt[tid] > 1) {
                int ix = atomicAdd(&s_namb, 1);
                s_amblist[ix] = tid;
            }
        }
        __syncthreads();
        // step 5: avg_p
        #pragma unroll
        for (int j = 0; j < 8; j++) {
            #pragma unroll
            for (int half = 0; half < 2; half++) {
                float tt = 0.0f;
                #pragma unroll
                for (int row_i = 0; row_i < 4; row_i++) {
                    const int mt = row_i >> 1, hr = row_i & 1;
                    tt += f[mt][j][hr * 2 + half] * finv[r0 + row_i * 8];
                }
                tt += __shfl_xor_sync(0xffffffffu, tt, 4);
                tt += __shfl_xor_sync(0xffffffffu, tt, 8);
                tt += __shfl_xor_sync(0xffffffffu, tt, 16);
                if (r0 == 0) atomicAdd(&g_avgp[wbase + j * 8 + 2 * q + half], tt);
            }
        }
        // step 6: inline fp32 refinement (warp per ambiguous row; x reloaded, L1-hot)
        const int na = s_namb;
        for (int a = wid; a < na; a += NWARP) {
            const int row = s_amblist[a];
            const int nc  = rowcnt[row];
            const int grow = rowbase + row;
            const float* xr = x + (size_t)grow * NIN;
            float best = -1e30f; int bestc = KDIM;
            if (nc <= 8) {
                for (int ti = 0; ti < nc; ti++) {
                    const int c = rowcols[row][ti];
                    const float* wr = W + (size_t)c * NIN;
                    float sm = 0.0f;
                    #pragma unroll 8
                    for (int u = 0; u < 32; u++)
                        sm = fmaf(xr[lane + u * 32], wr[lane + u * 32], sm);
                    #pragma unroll
                    for (int off = 16; off; off >>= 1)
                        sm += __shfl_xor_sync(0xffffffffu, sm, off);
                    float val = sm + bias[c] + gum[(size_t)grow * KDIM + c];
                    if (val > best || (val == best && c < bestc)) { best = val; bestc = c; }
                }
            } else {
                for (int c = 0; c < KDIM; c++) {
                    const float* wr = W + (size_t)c * NIN;
                    float sm = 0.0f;
                    #pragma unroll 8
                    for (int u = 0; u < 32; u++)
                        sm = fmaf(xr[lane + u * 32], wr[lane + u * 32], sm);
                    #pragma unroll
                    for (int off = 16; off; off >>= 1)
                        sm += __shfl_xor_sync(0xffffffffu, sm, off);
                    float val = sm + bias[c] + gum[(size_t)grow * KDIM + c];
                    if (val > best) { best = val; bestc = c; }
                }
            }
            if (lane == 0) srowm[row] = bestc;
        }
        __syncthreads();
        // step 7: m + z_q
        if (tid < 32) out[(size_t)B * EDIM + rowbase + tid] = (float)srowm[tid];
        #pragma unroll
        for (int g2 = 0; g2 < 4; g2++) {
            int idx = g2 * NTHREADS + tid;
            int row = idx >> 6, v = idx & 63;
            int arg = srowm[row];
            float4 cv = *(const float4*)(cb + (size_t)arg * EDIM + v * 4);
            *(float4*)(out + (size_t)(rowbase + row) * EDIM + v * 4) = cv;
        }
        __syncthreads();
    }

    // -------- diversity finisher --------
    __threadfence();
    if (tid == 0) {
        unsigned int old = atomicAdd(&g_count, 1u);
        sIsLast = (old == gridDim.x - 1) ? 1 : 0;
    }
    __syncthreads();
    if (sIsLast) {
        const float invB = 1.0f / (float)B;
        const float logK = logf((float)KDIM);
        float sdiv = 0.0f;
        for (int c = tid; c < KDIM; c += NTHREADS) {
            float p2 = g_avgp[c] * invB;
            sdiv += p2 * (logf(fmaxf(p2, 1e-9f)) + logK);
            g_avgp[c] = 0.0f;
        }
        #pragma unroll
        for (int off = 16; off; off >>= 1)
            sdiv += __shfl_xor_sync(0xffffffffu, sdiv, off);
        if (lane == 0) sred[wid] = sdiv;
        __syncthreads();
        if (tid == 0) {
            float tt = 0.0f;
            #pragma unroll
            for (int w = 0; w < NWARP; w++) tt += sred[w];
            size_t base = (size_t)B * EDIM + B;
            out[base]     = tt;
            out[base + 1] = 0.0f;
            g_count = 0u;
        }
    }
    CLUSTER_SYNC();
}

// ---------------- launch ----------------
extern "C" void kernel_launch(void* const* d_in, const int* in_sizes, int n_in,
                              void* d_out, int out_size) {
    const float* x    = (const float*)d_in[0];
    const float* gum  = (const float*)d_in[1];
    const float* W    = (const float*)d_in[2];
    const float* bias = (const float*)d_in[3];
    const float* cb   = (const float*)d_in[4];
    float* out = (float*)d_out;

    const int B = in_sizes[0] / NIN;             // 65536

    static int nsm = 0;
    if (nsm == 0) {
        cudaDeviceGetAttribute(&nsm, cudaDevAttrMultiProcessorCount, 0);
        nsm &= ~1;
        if (nsm <= 0) nsm = 148;
        cudaFuncSetAttribute(fused_vq_kernel, cudaFuncAttributeMaxDynamicSharedMemorySize, SMEM_DYN);
    }

    rearr_x_kernel<<<B / 16, 512>>>(x);
    rearr_w_kernel<<<KDIM / 16, 512>>>(W);
    fused_vq_kernel<<<nsm, NTHREADS, SMEM_DYN>>>(x, W, gum, bias, cb, out, B);
}

// round 13
// speedup vs baseline: 2.9816x; 1.9330x over previous
#include <cuda_runtime.h>
#include <cuda_bf16.h>
#include <math.h>
#include <stdint.h>

#define NIN   1024
#define KDIM  1024
#define EDIM  256
#define BM    32
#define NPAIRS 1024
#define ASLAB 1024                     // 32 rows x 32B bf16 per kchunk (16 k)
#define WSLAB 32768                    // 1024 ko x 32B bf16 per kchunk
#define ASTG  (2 * ASLAB)              // 2 kchunks per stage
#define WSTG  (2 * WSLAB)
#define STAGE (ASTG + WSTG)            // 67584
#define NSTAGE 3
#define SMEM_DYN (NSTAGE * STAGE)      // 202752
#define NTHREADS 512
#define NWARP 16
#define ITERS_PER_TILE 32
#define MARGIN 0.03f

// ---------------- device scratch ----------------
__device__ __align__(128) unsigned char g_xs[(size_t)2048 * 64 * ASLAB];  // 134MB
__device__ __align__(128) unsigned char g_ws[(size_t)64 * WSLAB];         // 2MB
__device__ float g_avgp[KDIM];
__device__ unsigned int g_count;

// ---------------- PTX helpers ----------------
__device__ __forceinline__ uint32_t smem_u32(const void* p) {
    uint32_t a;
    asm("{ .reg .u64 t; cvta.to.shared.u64 t, %1; cvt.u32.u64 %0, t; }" : "=r"(a) : "l"(p));
    return a;
}
__device__ __forceinline__ uint32_t cluster_rank() {
    uint32_t r; asm("mov.u32 %0, %%cluster_ctarank;" : "=r"(r)); return r;
}
#define MBAR_INIT(a, n) \
    asm volatile("mbarrier.init.shared.b64 [%0], %1;" :: "r"(a), "r"((uint32_t)(n)) : "memory")
#define MBAR_EXPECT_TX(a, b) \
    asm volatile("mbarrier.arrive.expect_tx.shared.b64 _, [%0], %1;" :: "r"(a), "r"((uint32_t)(b)) : "memory")
#define MBAR_ARRIVE_RANK(a, rk) \
    asm volatile("{ .reg .b32 ra; mapa.shared::cluster.u32 ra, %0, %1; " \
                 "mbarrier.arrive.shared::cluster.b64 _, [ra]; }" :: "r"(a), "r"(rk) : "memory")
#define MBAR_WAIT(a, p) do { \
    uint32_t _m = (a); uint32_t _p = (p); uint32_t _d; \
    asm volatile("{\n\t.reg .pred q;\n\tmbarrier.try_wait.parity.acquire.cta.shared::cta.b64 q, [%1], %2;\n\tselp.b32 %0,1,0,q;\n\t}" \
        : "=r"(_d) : "r"(_m), "r"(_p) : "memory"); \
    if (!_d) { \
        asm volatile("{\n\t.reg .pred Q;\n\tWL_%=:\n\tmbarrier.try_wait.parity.acquire.cta.shared::cta.b64 Q, [%0], %1, 0x989680;\n\t@Q bra.uni WD_%=;\n\tbra.uni WL_%=;\n\tWD_%=:\n\t}" \
            :: "r"(_m), "r"(_p) : "memory"); \
    } } while (0)
#define CLUSTER_SYNC() do { \
    asm volatile("barrier.cluster.arrive.aligned;" ::: "memory"); \
    asm volatile("barrier.cluster.wait.aligned;" ::: "memory"); } while (0)

__device__ __forceinline__ void bulk_g2s(uint32_t dst, const void* src, uint32_t bytes, uint32_t mbar) {
    asm volatile("cp.async.bulk.shared::cluster.global.mbarrier::complete_tx::bytes [%0], [%1], %2, [%3];"
        :: "r"(dst), "l"(src), "r"(bytes), "r"(mbar) : "memory");
}
__device__ __forceinline__ void bulk_g2s_mc(uint32_t dst, const void* src, uint32_t bytes, uint32_t mbar, uint16_t mask) {
    asm volatile("cp.async.bulk.shared::cluster.global.mbarrier::complete_tx::bytes.multicast::cluster [%0], [%1], %2, [%3], %4;"
        :: "r"(dst), "l"(src), "r"(bytes), "r"(mbar), "h"(mask) : "memory");
}

__device__ __forceinline__ void mma_bf16(float d[4], uint32_t a0, uint32_t a1, uint32_t a2, uint32_t a3,
                                         uint32_t b0, uint32_t b1) {
    asm volatile(
        "mma.sync.aligned.m16n8k16.row.col.f32.bf16.bf16.f32 "
        "{%0,%1,%2,%3}, {%4,%5,%6,%7}, {%8,%9}, {%0,%1,%2,%3};"
        : "+f"(d[0]), "+f"(d[1]), "+f"(d[2]), "+f"(d[3])
        : "r"(a0), "r"(a1), "r"(a2), "r"(a3), "r"(b0), "r"(b1));
}

__device__ __forceinline__ uint32_t packbf2(float lo, float hi) {
    __nv_bfloat162 h = __floats2bfloat162_rn(lo, hi);
    return *(uint32_t*)&h;
}
// slot s (0..7) holds k-pair c = (s>>1) + (s&1)*4 ;  kperm(c) = (c&3)*2 + (c>>2)
__device__ __forceinline__ int kperm(int c) { return (c & 3) * 2 + (c >> 2); }

// ---------------- rearrange x: warp-per-row, bf16 pack, no smem ----------------
__global__ __launch_bounds__(512) void rearr_x_kernel(const float* __restrict__ x) {
    const int tid = threadIdx.x;
    const int wid = tid >> 5, lane = tid & 31;
    const int row = blockIdx.x * 16 + wid;
    const int rt = row >> 5, rloc = row & 31;
    const float4* xr = (const float4*)(x + (size_t)row * NIN);

    float4 v[8];
    #pragma unroll
    for (int p = 0; p < 8; p++) v[p] = xr[lane + 32 * p];

    unsigned char* base = g_xs + (size_t)rt * 64 * ASLAB;
    #pragma unroll
    for (int p = 0; p < 8; p++) {
        int idx = lane + 32 * p;                 // float4 index within row
        int kchunk = idx >> 2, cc = idx & 3;
        unsigned char* dst = base + (size_t)(kchunk * 32 + rloc) * 32;
        *(uint32_t*)(dst + kperm(2 * cc) * 4)     = packbf2(v[p].x, v[p].y);
        *(uint32_t*)(dst + kperm(2 * cc + 1) * 4) = packbf2(v[p].z, v[p].w);
    }
}
// ---------------- rearrange W: warp-per-column, bf16 pack ----------------
__global__ __launch_bounds__(512) void rearr_w_kernel(const float* __restrict__ W) {
    const int tid = threadIdx.x;
    const int wid = tid >> 5, lane = tid & 31;
    const int ko = blockIdx.x * 16 + wid;
    const float4* wr = (const float4*)(W + (size_t)ko * NIN);

    float4 v[8];
    #pragma unroll
    for (int p = 0; p < 8; p++) v[p] = wr[lane + 32 * p];

    #pragma unroll
    for (int p = 0; p < 8; p++) {
        int idx = lane + 32 * p;
        int kchunk = idx >> 2, cc = idx & 3;
        unsigned char* dst = g_ws + (size_t)kchunk * WSLAB + ko * 32;
        *(uint32_t*)(dst + kperm(2 * cc) * 4)     = packbf2(v[p].x, v[p].y);
        *(uint32_t*)(dst + kperm(2 * cc + 1) * 4) = packbf2(v[p].z, v[p].w);
    }
}

// ---------------- persistent fused bf16 GEMM + epilogue + inline refine ----------------
__global__ __launch_bounds__(NTHREADS, 1) __cluster_dims__(2, 1, 1)
void fused_vq_kernel(const float* __restrict__ x, const float* __restrict__ W,
                     const float* __restrict__ gum, const float* __restrict__ bias,
                     const float* __restrict__ cb, float* __restrict__ out, int B)
{
    extern __shared__ __align__(128) unsigned char smem[];
    __shared__ __align__(8) unsigned long long mb_full[NSTAGE], mb_empty[NSTAGE];
    __shared__ float swmax[NWARP][32];
    __shared__ int   swarg[NWARP][32];
    __shared__ float swsum[NWARP][32];
    __shared__ float frow[32], finv[32];
    __shared__ int   rowcnt[32], srowm[32];
    __shared__ int   rowcols[32][8];
    __shared__ int   s_amblist[32];
    __shared__ int   s_namb;
    __shared__ float sred[NWARP];
    __shared__ int   sIsLast;

    const int tid  = threadIdx.x;
    const int wid  = tid >> 5;
    const int lane = tid & 31;
    const int r0   = lane >> 2;
    const int q    = lane & 3;
    const uint32_t rank = cluster_rank();
    const int cl   = blockIdx.x >> 1;
    const int ncl  = gridDim.x >> 1;
    const int wbase = wid * 64;

    const int ntiles = (NPAIRS - 1 - cl) / ncl + 1;
    const int total_its = ntiles * ITERS_PER_TILE;

    const uint32_t smem_b = smem_u32(smem);
    uint32_t full_a[NSTAGE], empty_a[NSTAGE];
    #pragma unroll
    for (int s = 0; s < NSTAGE; s++) {
        full_a[s]  = smem_u32(&mb_full[s]);
        empty_a[s] = smem_u32(&mb_empty[s]);
    }
    if (tid == 0) {
        #pragma unroll
        for (int s = 0; s < NSTAGE; s++) {
            MBAR_INIT(full_a[s], 1);
            MBAR_INIT(empty_a[s], 32);      // 16 warps x 2 CTAs arrive per round
        }
    }
    __syncthreads();
    CLUSTER_SYNC();

    const unsigned char* asrc = g_xs + (size_t)(2 * cl + rank) * 64 * ASLAB;

    if (tid == 0) {
        #pragma unroll
        for (int i = 0; i < NSTAGE; i++) {
            MBAR_EXPECT_TX(full_a[i], STAGE);
            bulk_g2s(smem_b + i * STAGE, asrc + (size_t)(2 * i) * ASLAB, ASTG, full_a[i]);
            bulk_g2s_mc(smem_b + i * STAGE + ASTG + rank * WSLAB,
                        g_ws + (size_t)(2 * i + rank) * WSLAB, WSLAB, full_a[i], (uint16_t)0x3);
        }
    }

    int it = 0, s = 0, ph = 0;
    for (int t = 0; t < ntiles; t++) {
        const int p = cl + t * ncl;
        const int rowbase = (2 * p + rank) * BM;

        // prefetch gum tile into L2 (consumed by epilogue ~65K cycles later)
        {
            const float* gp = gum + (size_t)rowbase * KDIM;
            #pragma unroll
            for (int pf = 0; pf < 2; pf++)
                asm volatile("prefetch.global.L2 [%0];"
                             :: "l"(gp + (size_t)(pf * NTHREADS + tid) * 32));
        }

        float f[2][8][4];
        #pragma unroll
        for (int m = 0; m < 2; m++)
            #pragma unroll
            for (int j = 0; j < 8; j++)
                #pragma unroll
                for (int v = 0; v < 4; v++) f[m][j][v] = 0.0f;

        // -------- barrier-free mainloop: 32 stage-iters x 2 kchunks --------
        for (int g = 0; g < ITERS_PER_TILE; g++) {
            MBAR_WAIT(full_a[s], ph);
            const uint32_t* base = (const uint32_t*)(smem + s * STAGE);
            #pragma unroll
            for (int kc = 0; kc < 2; kc++) {
                const uint32_t* As = base + kc * (ASLAB / 4);
                const uint32_t* Ws = base + (ASTG / 4) + kc * (WSLAB / 4);
                uint2 a[2][2];
                #pragma unroll
                for (int mt = 0; mt < 2; mt++) {
                    a[mt][0] = *(const uint2*)&As[(mt * 16 + r0) * 8 + 2 * q];
                    a[mt][1] = *(const uint2*)&As[(mt * 16 + r0 + 8) * 8 + 2 * q];
                }
                #pragma unroll
                for (int j = 0; j < 8; j++) {
                    uint2 b = *(const uint2*)&Ws[(wbase + j * 8 + r0) * 8 + 2 * q];
                    mma_bf16(f[0][j], a[0][0].x, a[0][1].x, a[0][0].y, a[0][1].y, b.x, b.y);
                    mma_bf16(f[1][j], a[1][0].x, a[1][1].x, a[1][0].y, a[1][1].y, b.x, b.y);
                }
            }
            // per-warp consumer arrival on both CTAs' empty barriers
            if (lane == 0) {
                MBAR_ARRIVE_RANK(empty_a[s], 0);
                MBAR_ARRIVE_RANK(empty_a[s], 1);
            }
            if (tid == 0) {
                const int git = it + NSTAGE;
                if (git < total_its) {
                    const int pi = git / ITERS_PER_TILE, gg = git % ITERS_PER_TILE;
                    const int pp = cl + pi * ncl;
                    MBAR_WAIT(empty_a[s], ph);          // all 32 warp-arrivals this round
                    MBAR_EXPECT_TX(full_a[s], STAGE);
                    bulk_g2s(smem_b + s * STAGE,
                             g_xs + ((size_t)(2 * pp + rank) * 64 + 2 * gg) * ASLAB,
                             ASTG, full_a[s]);
                    bulk_g2s_mc(smem_b + s * STAGE + ASTG + rank * WSLAB,
                                g_ws + (size_t)(2 * gg + rank) * WSLAB, WSLAB,
                                full_a[s], (uint16_t)0x3);
                }
            }
            it++; s++; if (s == NSTAGE) { s = 0; ph ^= 1; }
        }

        // -------- epilogue --------
        // step 1: + bias + gumbel; per-thread row max/arg
        float vmax[4]; int varg[4];
        #pragma unroll
        for (int row_i = 0; row_i < 4; row_i++) {
            const int grow = rowbase + r0 + row_i * 8;
            const int mt = row_i >> 1, hr = row_i & 1;
            float vm = -1e30f; int va = 0;
            #pragma unroll
            for (int j = 0; j < 8; j++) {
                const int col = wbase + j * 8 + 2 * q;
                float2 b2 = *(const float2*)(bias + col);
                float2 g2 = *(const float2*)(gum + (size_t)grow * KDIM + col);
                float v0 = f[mt][j][hr * 2 + 0] + b2.x + g2.x;
                float v1 = f[mt][j][hr * 2 + 1] + b2.y + g2.y;
                f[mt][j][hr * 2 + 0] = v0;
                f[mt][j][hr * 2 + 1] = v1;
                if (v0 > vm) { vm = v0; va = col; }
                if (v1 > vm) { vm = v1; va = col + 1; }
            }
            vmax[row_i] = vm; varg[row_i] = va;
        }
        #pragma unroll
        for (int off = 1; off <= 2; off <<= 1)
            #pragma unroll
            for (int row_i = 0; row_i < 4; row_i++) {
                float ov = __shfl_xor_sync(0xffffffffu, vmax[row_i], off);
                int   oa = __shfl_xor_sync(0xffffffffu, varg[row_i], off);
                if (ov > vmax[row_i] || (ov == vmax[row_i] && oa < varg[row_i])) {
                    vmax[row_i] = ov; varg[row_i] = oa;
                }
            }
        if (q == 0) {
            #pragma unroll
            for (int row_i = 0; row_i < 4; row_i++) {
                swmax[wid][r0 + row_i * 8] = vmax[row_i];
                swarg[wid][r0 + row_i * 8] = varg[row_i];
            }
        }
        __syncthreads();
        if (tid < 32) {
            float best = -1e30f; int barg = KDIM;
            #pragma unroll
            for (int w = 0; w < NWARP; w++) {
                float v = swmax[w][tid]; int a = swarg[w][tid];
                if (v > best || (v == best && a < barg)) { best = v; barg = a; }
            }
            frow[tid] = best; srowm[tid] = barg; rowcnt[tid] = 0;
            if (tid == 0) s_namb = 0;
        }
        __syncthreads();
        // step 3: candidates + exp + row partial sums
        float psum[4] = {0.f, 0.f, 0.f, 0.f};
        #pragma unroll
        for (int row_i = 0; row_i < 4; row_i++) {
            const int row = r0 + row_i * 8;
            const int mt = row_i >> 1, hr = row_i & 1;
            const float rm = frow[row];
            const float th = rm - MARGIN;
            #pragma unroll
            for (int j = 0; j < 8; j++) {
                #pragma unroll
                for (int half = 0; half < 2; half++) {
                    float v = f[mt][j][hr * 2 + half];
                    if (v >= th) {
                        int pos = atomicAdd(&rowcnt[row], 1);
                        if (pos < 8) rowcols[row][pos] = wbase + j * 8 + 2 * q + half;
                    }
                    float e = __expf(v - rm);
                    f[mt][j][hr * 2 + half] = e;
                    psum[row_i] += e;
                }
            }
        }
        #pragma unroll
        for (int off = 1; off <= 2; off <<= 1)
            #pragma unroll
            for (int row_i = 0; row_i < 4; row_i++)
                psum[row_i] += __shfl_xor_sync(0xffffffffu, psum[row_i], off);
        if (q == 0) {
            #pragma unroll
            for (int row_i = 0; row_i < 4; row_i++)
                swsum[wid][r0 + row_i * 8] = psum[row_i];
        }
        __syncthreads();
        if (tid < 32) {
            float sm = 0.0f;
            #pragma unroll
            for (int w = 0; w < NWARP; w++) sm += swsum[w][tid];
            finv[tid] = 1.0f / sm;
            if (rowcnt[tid] > 1) {
                int ix = atomicAdd(&s_namb, 1);
                s_amblist[ix] = tid;
            }
        }
        __syncthreads();
        // step 5: avg_p
        #pragma unroll
        for (int j = 0; j < 8; j++) {
            #pragma unroll
            for (int half = 0; half < 2; half++) {
                float tt = 0.0f;
                #pragma unroll
                for (int row_i = 0; row_i < 4; row_i++) {
                    const int mt = row_i >> 1, hr = row_i & 1;
                    tt += f[mt][j][hr * 2 + half] * finv[r0 + row_i * 8];
                }
                tt += __shfl_xor_sync(0xffffffffu, tt, 4);
                tt += __shfl_xor_sync(0xffffffffu, tt, 8);
                tt += __shfl_xor_sync(0xffffffffu, tt, 16);
                if (r0 == 0) atomicAdd(&g_avgp[wbase + j * 8 + 2 * q + half], tt);
            }
        }
        // step 6: inline fp32 refinement (warp per ambiguous row)
        const int na = s_namb;
        for (int a = wid; a < na; a += NWARP) {
            const int row = s_amblist[a];
            const int nc  = rowcnt[row];
            const int grow = rowbase + row;
            const float* xr = x + (size_t)grow * NIN;
            float best = -1e30f; int bestc = KDIM;
            if (nc <= 8) {
                for (int ti = 0; ti < nc; ti++) {
                    const int c = rowcols[row][ti];
                    const float* wr = W + (size_t)c * NIN;
                    float sm = 0.0f;
                    #pragma unroll 8
                    for (int u = 0; u < 32; u++)
                        sm = fmaf(xr[lane + u * 32], wr[lane + u * 32], sm);
                    #pragma unroll
                    for (int off = 16; off; off >>= 1)
                        sm += __shfl_xor_sync(0xffffffffu, sm, off);
                    float val = sm + bias[c] + gum[(size_t)grow * KDIM + c];
                    if (val > best || (val == best && c < bestc)) { best = val; bestc = c; }
                }
            } else {
                for (int c = 0; c < KDIM; c++) {
                    const float* wr = W + (size_t)c * NIN;
                    float sm = 0.0f;
                    #pragma unroll 8
                    for (int u = 0; u < 32; u++)
                        sm = fmaf(xr[lane + u * 32], wr[lane + u * 32], sm);
                    #pragma unroll
                    for (int off = 16; off; off >>= 1)
                        sm += __shfl_xor_sync(0xffffffffu, sm, off);
                    float val = sm + bias[c] + gum[(size_t)grow * KDIM + c];
                    if (val > best) { best = val; bestc = c; }
                }
            }
            if (lane == 0) srowm[row] = bestc;
        }
        __syncthreads();
        // step 7: m + z_q
        if (tid < 32) out[(size_t)B * EDIM + rowbase + tid] = (float)srowm[tid];
        #pragma unroll
        for (int g2 = 0; g2 < 4; g2++) {
            int idx = g2 * NTHREADS + tid;
            int row = idx >> 6, v = idx & 63;
            int arg = srowm[row];
            float4 cv = *(const float4*)(cb + (size_t)arg * EDIM + v * 4);
            *(float4*)(out + (size_t)(rowbase + row) * EDIM + v * 4) = cv;
        }
        __syncthreads();
    }

    // -------- diversity finisher --------
    __threadfence();
    if (tid == 0) {
        unsigned int old = atomicAdd(&g_count, 1u);
        sIsLast = (old == gridDim.x - 1) ? 1 : 0;
    }
    __syncthreads();
    if (sIsLast) {
        const float invB = 1.0f / (float)B;
        const float logK = logf((float)KDIM);
        float sdiv = 0.0f;
        for (int c = tid; c < KDIM; c += NTHREADS) {
            float p2 = g_avgp[c] * invB;
            sdiv += p2 * (logf(fmaxf(p2, 1e-9f)) + logK);
            g_avgp[c] = 0.0f;
        }
        #pragma unroll
        for (int off = 16; off; off >>= 1)
            sdiv += __shfl_xor_sync(0xffffffffu, sdiv, off);
        if (lane == 0) sred[wid] = sdiv;
        __syncthreads();
        if (tid == 0) {
            float tt = 0.0f;
            #pragma unroll
            for (int w = 0; w < NWARP; w++) tt += sred[w];
            size_t base = (size_t)B * EDIM + B;
            out[base]     = tt;
            out[base + 1] = 0.0f;
            g_count = 0u;
        }
    }
    CLUSTER_SYNC();
}

// ---------------- launch ----------------
extern "C" void kernel_launch(void* const* d_in, const int* in_sizes, int n_in,
                              void* d_out, int out_size) {
    const float* x    = (const float*)d_in[0];
    const float* gum  = (const float*)d_in[1];
    const float* W    = (const float*)d_in[2];
    const float* bias = (const float*)d_in[3];
    const float* cb   = (const float*)d_in[4];
    float* out = (float*)d_out;

    const int B = in_sizes[0] / NIN;             // 65536

    static int nsm = 0;
    if (nsm == 0) {
        cudaDeviceGetAttribute(&nsm, cudaDevAttrMultiProcessorCount, 0);
        nsm &= ~1;
        if (nsm <= 0) nsm = 148;
        cudaFuncSetAttribute(fused_vq_kernel, cudaFuncAttributeMaxDynamicSharedMemorySize, SMEM_DYN);
    }

    rearr_x_kernel<<<B / 16, 512>>>(x);
    rearr_w_kernel<<<KDIM / 16, 512>>>(W);
    fused_vq_kernel<<<nsm, NTHREADS, SMEM_DYN>>>(x, W, gum, bias, cb, out, B);
}